// round 1
// baseline (speedup 1.0000x reference)
#include <cuda_runtime.h>

// Problem constants (from reference)
#define UPDATE_SIZE 4096
#define BATCH 256
#define NUM_UPD 16
#define SNAP_SIZE (UPDATE_SIZE * NUM_UPD)                   // 65536
#define OUT_SIZE (UPDATE_SIZE * BATCH)                      // 1048576
#define SNAP_LEN (SNAP_SIZE + (BATCH - 1) * UPDATE_SIZE)    // 1110016
#define SNAP_V4 (SNAP_LEN / 4)                              // 277504
#define ZERO_V4 (OUT_SIZE / 4)                              // 262144
#define V4_PER_BLK (UPDATE_SIZE / 4)                        // 1024
#define UPD_ROW_V4 (SNAP_SIZE / 4)                          // 16384
// float4 stride in update between consecutive contributing rows i for a fixed
// snap position: i*16384 + (b-i)*1024 + r  =  i*15360 + b*1024 + r
#define I_STRIDE_V4 (UPD_ROW_V4 - V4_PER_BLK)               // 15360

__global__ __launch_bounds__(256) void online_avg_kernel(
    const float4* __restrict__ upd,    // (256, 65536) as float4
    const float4* __restrict__ snap,   // (1110016,) as float4
    const float* __restrict__ idxp,    // (1,)
    float4* __restrict__ out4,
    float* __restrict__ out)
{
    int t = blockIdx.x * blockDim.x + threadIdx.x;

    if (t < SNAP_V4) {
        // Snapshot-recurrence role: one thread per 4 consecutive snap elements.
        int b = t >> 10;         // snap block index, 0..270
        int r = t & 1023;        // float4 column within block
        float idx0 = __ldg(idxp);

        float4 s = snap[t];
        int base = b * V4_PER_BLK + r;   // max ~4.19M, fits int

        #pragma unroll
        for (int k = 0; k < 16; ++k) {
            int i = b - 15 + k;          // scan step touching this element
            if (i >= 0 && i < BATCH) {
                float4 x = __ldg(&upd[base + i * I_STRIDE_V4]);
                // norm value here is 16-(b-i) = k+1 exactly
                float wt = fminf((float)(k + 1), idx0 + (float)i + 1.0f);
                float rw = 1.0f / wt;
                s.x = fmaf(x.x - s.x, rw, s.x);
                s.y = fmaf(x.y - s.y, rw, s.y);
                s.z = fmaf(x.z - s.z, rw, s.z);
                s.w = fmaf(x.w - s.w, rw, s.w);
            }
        }
        // d_out[p] = snap_final[p] for p < SNAP_LEN covers both the `output`
        // tensor [0, OUT_SIZE) and new_snapshot's live prefix [OUT_SIZE, SNAP_LEN).
        out4[t] = s;
    } else {
        // Zero-fill role: new_snapshot tail = zeros(OUT_SIZE), plus the scalar.
        int z = t - SNAP_V4;
        if (z < ZERO_V4) {
            out4[SNAP_V4 + z] = make_float4(0.f, 0.f, 0.f, 0.f);
        }
        if (z == 0) {
            out[OUT_SIZE + SNAP_LEN] = __ldg(idxp) + (float)BATCH;
        }
    }
}

extern "C" void kernel_launch(void* const* d_in, const int* in_sizes, int n_in,
                              void* d_out, int out_size)
{
    const float4* upd  = (const float4*)d_in[0];
    const float4* snap = (const float4*)d_in[1];
    const float*  idxp = (const float*)d_in[2];

    float4* out4 = (float4*)d_out;
    float*  out  = (float*)d_out;

    const int total_threads = SNAP_V4 + ZERO_V4;      // 539648
    const int threads = 256;
    const int blocks = (total_threads + threads - 1) / threads;  // 2108

    online_avg_kernel<<<blocks, threads>>>(upd, snap, idxp, out4, out);
}